// round 1
// baseline (speedup 1.0000x reference)
#include <cuda_runtime.h>

#define NMAX   100000
#define DIN    64
#define NHEAD  4
#define HDIM   16
#define FEAT   64   // NHEAD*HDIM

// -------- scratch (static device globals; no allocations allowed) ----------
__device__ __align__(16) static float g_h[(size_t)NMAX * FEAT];   // projected node features
__device__ static float g_u[NMAX];
__device__ static float g_v[NMAX];
__device__ __align__(16) static float g_as[NMAX * NHEAD];
__device__ __align__(16) static float g_ad[NMAX * NHEAD];
__device__ static float g_denom[NMAX * NHEAD];

struct Params {
    float cu[DIN];   // Wd @ (Wf[0:64]  + Wf[128:192])
    float cv[DIN];   // Wd @ (Wf[64:128] - Wf[128:192])
    float off;       // bd . (wfu + wfv) + bf
    float ba;        // attention bias scalar
};
__device__ static Params g_P;

// ---------------------------------------------------------------------------
// 1) Fold the rank-1 edge linears into per-node projection vectors.
// ---------------------------------------------------------------------------
__global__ void precompute_kernel(const float* __restrict__ Wd,
                                  const float* __restrict__ bd,
                                  const float* __restrict__ Wf,
                                  const float* __restrict__ bf,
                                  const float* __restrict__ ba) {
    __shared__ float wfu[DIN], wfv[DIN], red[DIN];
    int t = threadIdx.x;   // 64 threads
    float f0 = Wf[t], f1 = Wf[DIN + t], f2 = Wf[2 * DIN + t];
    wfu[t] = f0 + f2;
    wfv[t] = f1 - f2;
    __syncthreads();
    float cu = 0.f, cv = 0.f;
#pragma unroll 8
    for (int j = 0; j < DIN; j++) {
        float w = Wd[t * DIN + j];
        cu += w * wfu[j];
        cv += w * wfv[j];
    }
    g_P.cu[t] = cu;
    g_P.cv[t] = cv;
    red[t] = bd[t] * (wfu[t] + wfv[t]);
    __syncthreads();
    if (t == 0) {
        float s = bf[0];
        for (int j = 0; j < DIN; j++) s += red[j];
        g_P.off = s;
        g_P.ba  = ba[0];
    }
}

// ---------------------------------------------------------------------------
// 2) Zero the accumulators (d_out is poisoned by the harness).
// ---------------------------------------------------------------------------
__global__ void zero_kernel(float* __restrict__ out, int n_out, int n_den) {
    int i = blockIdx.x * blockDim.x + threadIdx.x;
    int stride = gridDim.x * blockDim.x;
    for (int k = i; k < n_out; k += stride) out[k] = 0.f;
    for (int k = i; k < n_den; k += stride) g_denom[k] = 0.f;
}

// ---------------------------------------------------------------------------
// 3) Per-node projections: h = x@Wl + bl, u = x.cu, v = x.cv,
//    a_s/a_d = per-head dot with Wa halves.
// ---------------------------------------------------------------------------
__global__ void __launch_bounds__(128)
node_kernel(const float* __restrict__ x,
            const float* __restrict__ Wl,
            const float* __restrict__ bl,
            const float* __restrict__ Wa,
            int N) {
    __shared__ float s_wl[DIN * FEAT];
    __shared__ float s_bl[FEAT];
    __shared__ float s_wa[2 * HDIM];
    __shared__ float s_cu[DIN], s_cv[DIN];

    for (int i = threadIdx.x; i < DIN * FEAT; i += blockDim.x) s_wl[i] = Wl[i];
    if (threadIdx.x < FEAT) {
        s_bl[threadIdx.x] = bl[threadIdx.x];
        s_cu[threadIdx.x] = g_P.cu[threadIdx.x];
        s_cv[threadIdx.x] = g_P.cv[threadIdx.x];
    }
    if (threadIdx.x < 2 * HDIM) s_wa[threadIdx.x] = Wa[threadIdx.x];
    __syncthreads();

    int n = blockIdx.x * blockDim.x + threadIdx.x;
    if (n >= N) return;

    float acc[FEAT];
#pragma unroll
    for (int o = 0; o < FEAT; o++) acc[o] = s_bl[o];
    float u = 0.f, v = 0.f;

    const float4* xr = reinterpret_cast<const float4*>(x + (size_t)n * DIN);
#pragma unroll 1
    for (int i4 = 0; i4 < DIN / 4; i4++) {
        float4 xv = xr[i4];
        float xs[4] = {xv.x, xv.y, xv.z, xv.w};
#pragma unroll
        for (int j = 0; j < 4; j++) {
            int i = i4 * 4 + j;
            float xi = xs[j];
            u += xi * s_cu[i];
            v += xi * s_cv[i];
            const float4* wrow = reinterpret_cast<const float4*>(&s_wl[i * FEAT]);
#pragma unroll
            for (int o4 = 0; o4 < FEAT / 4; o4++) {
                float4 wv = wrow[o4];
                acc[o4 * 4 + 0] += xi * wv.x;
                acc[o4 * 4 + 1] += xi * wv.y;
                acc[o4 * 4 + 2] += xi * wv.z;
                acc[o4 * 4 + 3] += xi * wv.w;
            }
        }
    }

    float4* hout = reinterpret_cast<float4*>(&g_h[(size_t)n * FEAT]);
#pragma unroll
    for (int o4 = 0; o4 < FEAT / 4; o4++)
        hout[o4] = make_float4(acc[o4 * 4 + 0], acc[o4 * 4 + 1],
                               acc[o4 * 4 + 2], acc[o4 * 4 + 3]);

    g_u[n] = u;
    g_v[n] = v;

#pragma unroll
    for (int h = 0; h < NHEAD; h++) {
        float as = 0.f, ad = 0.f;
#pragma unroll
        for (int k = 0; k < HDIM; k++) {
            float hv = acc[h * HDIM + k];
            as += hv * s_wa[k];
            ad += hv * s_wa[HDIM + k];
        }
        g_as[n * NHEAD + h] = as;
        g_ad[n * NHEAD + h] = ad;
    }
}

// ---------------------------------------------------------------------------
// 4) Edge pass: 16 threads per edge (head = t/4, quarter = t%4).
//    No segment-max needed (alpha is O(1); softmax ratio is max-invariant).
// ---------------------------------------------------------------------------
__global__ void __launch_bounds__(256)
edge_kernel(const int* __restrict__ src, const int* __restrict__ dst,
            float* __restrict__ out, int E) {
    int gid = blockIdx.x * blockDim.x + threadIdx.x;
    int eid = gid >> 4;
    if (eid >= E) return;
    int t = gid & 15;
    int head = t >> 2;
    int q = t & 3;

    int s = __ldg(&src[eid]);
    int d = __ldg(&dst[eid]);

    float arg = g_u[s] + g_v[d] + g_P.off;
    float sg = (arg > 0.f) ? 1.f : ((arg < 0.f) ? -1.f : 0.f);

    float al = sg * g_as[s * NHEAD + head] + g_ad[d * NHEAD + head] + g_P.ba;
    al = (al > 0.f) ? al : 0.01f * al;      // leaky_relu
    float w = __expf(al);

    const float4 hv =
        *reinterpret_cast<const float4*>(&g_h[(size_t)s * FEAT + head * HDIM + q * 4]);
    float ws = w * sg;
    float4 val = make_float4(ws * hv.x, ws * hv.y, ws * hv.z, ws * hv.w);

    float* p = &out[(size_t)d * FEAT + head * HDIM + q * 4];
    asm volatile("red.global.add.v4.f32 [%0], {%1,%2,%3,%4};"
                 :: "l"(p), "f"(val.x), "f"(val.y), "f"(val.z), "f"(val.w)
                 : "memory");
    if (q == 0) {
        float* pd = &g_denom[d * NHEAD + head];
        asm volatile("red.global.add.f32 [%0], %1;" :: "l"(pd), "f"(w) : "memory");
    }
}

// ---------------------------------------------------------------------------
// 5) Normalize: out = num / max(denom, 1e-16)
// ---------------------------------------------------------------------------
__global__ void final_kernel(float* __restrict__ out, int total) {
    int idx = blockIdx.x * blockDim.x + threadIdx.x;
    if (idx >= total) return;
    int n = idx >> 6;            // /64
    int head = (idx >> 4) & 3;   // (idx/16)%4
    float dn = g_denom[n * NHEAD + head];
    out[idx] = out[idx] / fmaxf(dn, 1e-16f);
}

// ---------------------------------------------------------------------------
extern "C" void kernel_launch(void* const* d_in, const int* in_sizes, int n_in,
                              void* d_out, int out_size) {
    const float* x   = (const float*)d_in[0];
    const int*   src = (const int*)  d_in[1];
    const int*   dst = (const int*)  d_in[2];
    const float* Wl  = (const float*)d_in[3];
    const float* bl  = (const float*)d_in[4];
    const float* Wa  = (const float*)d_in[5];
    const float* ba  = (const float*)d_in[6];
    const float* Wd  = (const float*)d_in[7];
    const float* bd  = (const float*)d_in[8];
    const float* Wf  = (const float*)d_in[9];
    const float* bf  = (const float*)d_in[10];
    float* out = (float*)d_out;

    int N = in_sizes[0] / DIN;
    int E = in_sizes[1];

    precompute_kernel<<<1, 64>>>(Wd, bd, Wf, bf, ba);
    zero_kernel<<<2048, 256>>>(out, N * FEAT, N * NHEAD);
    node_kernel<<<(N + 127) / 128, 128>>>(x, Wl, bl, Wa, N);
    {
        long long threads = (long long)E * 16;
        int blocks = (int)((threads + 255) / 256);
        edge_kernel<<<blocks, 256>>>(src, dst, out, E);
    }
    final_kernel<<<(N * FEAT + 255) / 256, 256>>>(out, N * FEAT);
}